// round 15
// baseline (speedup 1.0000x reference)
#include <cuda_runtime.h>
#include <cuda_bf16.h>

#define N_NODES 20000
#define N_EDGES 200000
#define IN_DIM  500
#define HID     256
#define OUT_DIM 16
#define MHD     64

// ---------------- device scratch (static, no allocations) ----------------
struct ZS {                     // zeroed by ONE memset each launch
    int   cnt[N_NODES];
    float D[N_NODES * 16];      // per-node sum of P (src) + S (dst); symmetric
};
__device__ ZS    g_zs;
__device__ float g_h  [N_NODES * HID];     // h, then xb (updated in place)
__device__ float g_h1 [N_NODES * MHD];     // MLP intermediates
__device__ float g_p0 [N_NODES * MHD];     // split-K partials for input MLP
__device__ float g_p1 [N_NODES * MHD];
__device__ float g_AB [N_NODES * 2 * MHD]; // [N][128]: A | B
__device__ float g_Wc [2 * MHD * MHD];     // combined (Wab @ Win2) -> [128][64]
__device__ float g_bc [2 * MHD];           // combined bias Wab @ bin2
__device__ float g_Q  [(size_t)N_EDGES * 32]; // per edge: Q row-major, Q^T row-major
__device__ float g_H  [N_NODES * HID];     // diffusion operand H (layer 0)
__device__ float g_H2 [N_NODES * HID];     // diffusion operand H (layer 1)
__device__ int   g_off[N_NODES + 1];
__device__ int   g_cur[N_NODES];
__device__ int2  g_incid[2 * N_EDGES];     // {(e<<1)|role, other}

// ---------------- SGEMM: C = act(A[M,K](lda) @ W[N,K](ldw)^T + b) --------
template<bool RELU>
__global__ __launch_bounds__(256, 2)
void sgemm128(const float* __restrict__ A, const float* __restrict__ W,
              const float* __restrict__ bias, float* __restrict__ C,
              int M, int N, int K, int lda, int ldw)
{
    __shared__ float As[16][132];
    __shared__ float Ws[16][68];

    int tid = threadIdx.x;
    int tx = tid & 15, ty = tid >> 4;
    int row0 = blockIdx.y * 128, col0 = blockIdx.x * 64;

    int arow = tid >> 1;
    int akb  = (tid & 1) * 8;
    int wcol = tid & 63;
    int wkb  = (tid >> 6) * 4;

    int gr = row0 + arow;
    int gc = col0 + wcol;
    const float* Arow = A + (size_t)(gr < M ? gr : 0) * lda;
    const float* Wrow = W + (size_t)(gc < N ? gc : 0) * ldw;
    bool rok = gr < M;
    bool cok = gc < N;

    float acc[8][4] = {};
    float ra[8], rw[4];

    #pragma unroll
    for (int u = 0; u < 8; u++) {
        int k = akb + u;
        ra[u] = (rok && k < K) ? Arow[k] : 0.f;
    }
    #pragma unroll
    for (int u = 0; u < 4; u++) {
        int k = wkb + u;
        rw[u] = (cok && k < K) ? Wrow[k] : 0.f;
    }

    for (int k0 = 0; k0 < K; k0 += 16) {
        #pragma unroll
        for (int u = 0; u < 8; u++) As[akb + u][arow] = ra[u];
        #pragma unroll
        for (int u = 0; u < 4; u++) Ws[wkb + u][wcol] = rw[u];
        __syncthreads();

        int kn = k0 + 16;
        if (kn < K) {
            #pragma unroll
            for (int u = 0; u < 8; u++) {
                int k = kn + akb + u;
                ra[u] = (rok && k < K) ? Arow[k] : 0.f;
            }
            #pragma unroll
            for (int u = 0; u < 4; u++) {
                int k = kn + wkb + u;
                rw[u] = (cok && k < K) ? Wrow[k] : 0.f;
            }
        }

        #pragma unroll
        for (int kk = 0; kk < 16; kk++) {
            float4 a0 = *(const float4*)&As[kk][ty * 8];
            float4 a1 = *(const float4*)&As[kk][ty * 8 + 4];
            float4 b0 = *(const float4*)&Ws[kk][tx * 4];
            float a[8] = {a0.x, a0.y, a0.z, a0.w, a1.x, a1.y, a1.z, a1.w};
            float b[4] = {b0.x, b0.y, b0.z, b0.w};
            #pragma unroll
            for (int i = 0; i < 8; i++)
                #pragma unroll
                for (int j = 0; j < 4; j++)
                    acc[i][j] += a[i] * b[j];
        }
        __syncthreads();
    }

    #pragma unroll
    for (int i = 0; i < 8; i++) {
        int r = row0 + ty * 8 + i;
        if (r >= M) continue;
        #pragma unroll
        for (int j = 0; j < 4; j++) {
            int c = col0 + tx * 4 + j;
            if (c >= N) continue;
            float v = acc[i][j] + (bias ? bias[c] : 0.f);
            if (RELU) v = fmaxf(v, 0.f);
            C[(size_t)r * N + c] = v;
        }
    }
}

// ---------------- fused output MLP (row-block base for split) ------------
__global__ __launch_bounds__(256, 2)
void outmlp_kernel(const float* __restrict__ A,  const float* __restrict__ W1,
                   const float* __restrict__ b1v, const float* __restrict__ W2,
                   const float* __restrict__ b2v, float* __restrict__ C,
                   int bbase)
{
    __shared__ float buf[128 * 68];
    __shared__ float W2t[64 * 16];
    float (*As)[132] = (float(*)[132])buf;
    float (*Ws)[68]  = (float(*)[68])(buf + 16 * 132);

    const int M = N_NODES, K = 256;
    int tid = threadIdx.x;
    for (int i = tid; i < 1024; i += 256)
        W2t[(i & 63) * 16 + (i >> 6)] = W2[i];

    int tx = tid & 15, ty = tid >> 4;
    int row0 = (bbase + blockIdx.x) * 128;
    int arow = tid >> 1;
    int akb  = (tid & 1) * 8;
    int wcol = tid & 63;
    int wkb  = (tid >> 6) * 4;

    int gr = row0 + arow;
    const float* Arow = A + (size_t)(gr < M ? gr : 0) * 256;
    const float* Wrow = W1 + (size_t)wcol * 256;
    bool rok = gr < M;

    float acc[8][4] = {};
    float ra[8], rw[4];
    #pragma unroll
    for (int u = 0; u < 8; u++) ra[u] = rok ? Arow[akb + u] : 0.f;
    #pragma unroll
    for (int u = 0; u < 4; u++) rw[u] = Wrow[wkb + u];

    for (int k0 = 0; k0 < K; k0 += 16) {
        #pragma unroll
        for (int u = 0; u < 8; u++) As[akb + u][arow] = ra[u];
        #pragma unroll
        for (int u = 0; u < 4; u++) Ws[wkb + u][wcol] = rw[u];
        __syncthreads();

        int kn = k0 + 16;
        if (kn < K) {
            #pragma unroll
            for (int u = 0; u < 8; u++) ra[u] = rok ? Arow[kn + akb + u] : 0.f;
            #pragma unroll
            for (int u = 0; u < 4; u++) rw[u] = Wrow[kn + wkb + u];
        }

        #pragma unroll
        for (int kk = 0; kk < 16; kk++) {
            float4 a0 = *(const float4*)&As[kk][ty * 8];
            float4 a1 = *(const float4*)&As[kk][ty * 8 + 4];
            float4 b0 = *(const float4*)&Ws[kk][tx * 4];
            float a[8] = {a0.x, a0.y, a0.z, a0.w, a1.x, a1.y, a1.z, a1.w};
            float b[4] = {b0.x, b0.y, b0.z, b0.w};
            #pragma unroll
            for (int i = 0; i < 8; i++)
                #pragma unroll
                for (int j = 0; j < 4; j++)
                    acc[i][j] += a[i] * b[j];
        }
        __syncthreads();
    }

    float* h1s = buf;
    #pragma unroll
    for (int i = 0; i < 8; i++) {
        int r = ty * 8 + i;
        #pragma unroll
        for (int j = 0; j < 4; j++) {
            int c = tx * 4 + j;
            h1s[r * 68 + c] = fmaxf(acc[i][j] + b1v[c], 0.f);
        }
    }
    __syncthreads();

    int row = tid >> 1, ch = tid & 1;
    float a8[8] = {};
    #pragma unroll 8
    for (int k = 0; k < 64; k++) {
        float hv = h1s[row * 68 + k];
        float4 wA = *(const float4*)&W2t[k * 16 + ch * 8];
        float4 wB = *(const float4*)&W2t[k * 16 + ch * 8 + 4];
        a8[0] += hv * wA.x; a8[1] += hv * wA.y;
        a8[2] += hv * wA.z; a8[3] += hv * wA.w;
        a8[4] += hv * wB.x; a8[5] += hv * wB.y;
        a8[6] += hv * wB.z; a8[7] += hv * wB.w;
    }
    int gr2 = row0 + row;
    if (gr2 < M) {
        float4 bA = *(const float4*)&b2v[ch * 8];
        float4 bB = *(const float4*)&b2v[ch * 8 + 4];
        float4 oA = make_float4(a8[0] + bA.x, a8[1] + bA.y, a8[2] + bA.z, a8[3] + bA.w);
        float4 oB = make_float4(a8[4] + bB.x, a8[5] + bB.y, a8[6] + bB.z, a8[7] + bB.w);
        *(float4*)&C[(size_t)gr2 * 16 + ch * 8]     = oA;
        *(float4*)&C[(size_t)gr2 * 16 + ch * 8 + 4] = oB;
    }
}

// ---------------- combine split-K partials: h1 = relu(p0+p1+bias) --------
__global__ __launch_bounds__(256)
void combine_kernel(const float* __restrict__ bias)
{
    int i = blockIdx.x * 256 + threadIdx.x;
    float4 a = ((const float4*)g_p0)[i];
    float4 b = ((const float4*)g_p1)[i];
    float4 bs = *(const float4*)&bias[(i * 4) & 63];
    float4 r;
    r.x = fmaxf(a.x + b.x + bs.x, 0.f);
    r.y = fmaxf(a.y + b.y + bs.y, 0.f);
    r.z = fmaxf(a.z + b.z + bs.z, 0.f);
    r.w = fmaxf(a.w + b.w + bs.w, 0.f);
    ((float4*)g_h1)[i] = r;
}

// ---------------- CSR build ----------------
__global__ void count_kernel(const int* __restrict__ ei) {
    int e = blockIdx.x * 256 + threadIdx.x;
    if (e < N_EDGES) {
        atomicAdd(&g_zs.cnt[ei[e]], 1);
        atomicAdd(&g_zs.cnt[ei[N_EDGES + e]], 1);
    }
}

__global__ void scan_kernel() {
    const int CH = (N_NODES + 1023) / 1024;  // 20
    __shared__ int ssum[1024];
    int tid = threadIdx.x;
    int begin = tid * CH;
    int endi = begin + CH; if (endi > N_NODES) endi = N_NODES;
    int s = 0;
    for (int i = begin; i < endi; i++) s += g_zs.cnt[i];
    ssum[tid] = s;
    __syncthreads();
    for (int off = 1; off < 1024; off <<= 1) {
        int v = 0;
        if (tid >= off) v = ssum[tid - off];
        __syncthreads();
        ssum[tid] += v;
        __syncthreads();
    }
    int run = ssum[tid] - s;
    for (int i = begin; i < endi; i++) {
        g_off[i] = run;
        g_cur[i] = run;
        run += g_zs.cnt[i];
    }
    if (tid == 1023) g_off[N_NODES] = ssum[1023];
}

__global__ void fill_kernel(const int* __restrict__ ei) {
    int e = blockIdx.x * 256 + threadIdx.x;
    if (e < N_EDGES) {
        int s = ei[e], d = ei[N_EDGES + e];
        int p = atomicAdd(&g_cur[s], 1);
        g_incid[p] = make_int2(e << 1, d);
        int p2 = atomicAdd(&g_cur[d], 1);
        g_incid[p2] = make_int2((e << 1) | 1, s);
    }
}

// ---------------- combined weights: Wc = Wab @ Win2, bc = Wab @ bin2 -----
__global__ __launch_bounds__(256)
void wc_kernel(const float* __restrict__ Wm1,
               const float* __restrict__ Win2,
               const float* __restrict__ bin2)
{
    __shared__ float part[256];
    __shared__ float bpart[64];
    int i = blockIdx.x;
    const float* wrow = (i < 64) ? &Wm1[i * 512] : &Wm1[(i - 64) * 512 + 256];
    int t = threadIdx.x;
    int mh = t & 63, kq = t >> 6;
    float s = 0.f;
    #pragma unroll 16
    for (int k = kq * 64; k < kq * 64 + 64; k++)
        s += wrow[k] * Win2[k * 64 + mh];
    part[t] = s;
    if (kq == 0) {
        float b = 0.f;
        #pragma unroll
        for (int k = mh * 4; k < mh * 4 + 4; k++) b += wrow[k] * bin2[k];
        bpart[mh] = b;
    }
    __syncthreads();
    if (kq == 0)
        g_Wc[i * 64 + mh] = part[mh] + part[64 + mh] + part[128 + mh] + part[192 + mh];
    if (t == 0) {
        float bb = 0.f;
        #pragma unroll
        for (int k = 0; k < 64; k++) bb += bpart[k];
        g_bc[i] = bb;
    }
}

// ---------------- per-edge v4: weights-in-regs, 20 edges/warp, shfl fsft -
__global__ __launch_bounds__(256, 2)
void edge_kernel(const int* __restrict__ ei, const float* __restrict__ Wm2,
                 const float* __restrict__ bm1, const float* __restrict__ bm2)
{
    __shared__ float W4s[1024];
    __shared__ float sbuf[8 * 128];
    int tid = threadIdx.x;
    for (int idx = tid; idx < 1024; idx += 256) {
        int o = idx >> 6, k = idx & 63;
        W4s[((k >> 2) << 6) + (o << 2) + (k & 3)] = Wm2[idx];
    }
    __syncthreads();

    int warp = tid >> 5, lane = tid & 31;
    int o = lane & 15;
    float* sw = &sbuf[warp * 128];
    int k0 = lane * 2;

    float4 wreg[16];
    #pragma unroll
    for (int kc = 0; kc < 16; kc++)
        wreg[kc] = *(const float4*)&W4s[kc * 64 + o * 4];
    float2 b1 = *(const float2*)&bm1[k0];
    float bm2o = __ldg(&bm2[o]);
    int i = o >> 2, j = o & 3;

    const int EPW = 20;
    int e0 = (blockIdx.x * 8 + warp) * EPW;  // grid 1250, exact

    int sA = ei[e0], dA = ei[N_EDGES + e0];
    float2 AsA = *(const float2*)&g_AB[sA * 128 + k0];
    float2 BdA = *(const float2*)&g_AB[dA * 128 + 64 + k0];
    float2 AdA = *(const float2*)&g_AB[dA * 128 + k0];
    float2 BsA = *(const float2*)&g_AB[sA * 128 + 64 + k0];

    #pragma unroll 4
    for (int t = 0; t < EPW; t++) {
        int e = e0 + t;
        int sB = 0, dB = 0;
        float2 AsB, BdB, AdB, BsB;
        if (t < EPW - 1) {
            sB = ei[e + 1]; dB = ei[N_EDGES + e + 1];
            AsB = *(const float2*)&g_AB[sB * 128 + k0];
            BdB = *(const float2*)&g_AB[dB * 128 + 64 + k0];
            AdB = *(const float2*)&g_AB[dB * 128 + k0];
            BsB = *(const float2*)&g_AB[sB * 128 + 64 + k0];
        }

        float2 t1v = make_float2(fmaxf(AsA.x + BdA.x + b1.x, 0.f),
                                 fmaxf(AsA.y + BdA.y + b1.y, 0.f));
        float2 t2v = make_float2(fmaxf(AdA.x + BsA.x + b1.x, 0.f),
                                 fmaxf(AdA.y + BsA.y + b1.y, 0.f));
        __syncwarp();
        *(float2*)&sw[k0]      = t1v;
        *(float2*)&sw[64 + k0] = t2v;
        __syncwarp();

        const float* tv = sw + ((lane >> 4) << 6);
        float accf = 0.f;
        #pragma unroll
        for (int kc = 0; kc < 16; kc++) {
            float4 tval = *(const float4*)&tv[kc * 4];
            float4 w = wreg[kc];
            accf += tval.x * w.x + tval.y * w.y + tval.z * w.z + tval.w * w.w;
        }
        accf += bm2o;

        float p = 0.f, q = 0.f, ss = 0.f;
        #pragma unroll
        for (int m = 0; m < 4; m++) {
            float fsi = __shfl_sync(0xffffffffu, accf, m * 4 + i);
            float fsj = __shfl_sync(0xffffffffu, accf, m * 4 + j);
            float fti = __shfl_sync(0xffffffffu, accf, 16 + m * 4 + i);
            float ftj = __shfl_sync(0xffffffffu, accf, 16 + m * 4 + j);
            p  += fsi * fsj;
            q  += fsi * ftj;
            ss += fti * ftj;
        }
        if (lane < 16) {
            float* qb = &g_Q[(size_t)e * 32];
            qb[lane] = q;
            qb[16 + j * 4 + i] = q;
            atomicAdd(&g_zs.D[sA * 16 + lane], p);
            atomicAdd(&g_zs.D[dA * 16 + lane], ss);
        }

        sA = sB; dA = dB;
        AsA = AsB; BdA = BdB; AdA = AdB; BsA = BsB;
    }
}

// ---------------- per-node H = (Wd1^T @ xb) @ Wd2^T -> Hout --------------
__global__ __launch_bounds__(256)
void hcomp_kernel(const float* __restrict__ Wd1, const float* __restrict__ Wd2,
                  int layer, float* __restrict__ Hout, int nbase)
{
    __shared__ float w2s[64 * 65];
    __shared__ float h1s[8][4][64];
    int tid = threadIdx.x;
    for (int idx = tid; idx < 4096; idx += 256) {
        int g = idx >> 6, f = idx & 63;
        w2s[g * 65 + f] = Wd2[layer * 4096 + idx];
    }
    float wd1[16];
    #pragma unroll
    for (int i = 0; i < 16; i++) wd1[i] = __ldg(&Wd1[layer * 16 + i]);

    int warp = tid >> 5, lane = tid & 31;
    int n = nbase + blockIdx.x * 8 + warp;
    int c0 = lane * 2;
    float2 xv[4];
    #pragma unroll
    for (int j = 0; j < 4; j++)
        xv[j] = *(const float2*)&g_h[n * 256 + j * 64 + c0];
    #pragma unroll
    for (int i = 0; i < 4; i++) {
        h1s[warp][i][c0]     = wd1[i] * xv[0].x + wd1[4 + i] * xv[1].x +
                               wd1[8 + i] * xv[2].x + wd1[12 + i] * xv[3].x;
        h1s[warp][i][c0 + 1] = wd1[i] * xv[0].y + wd1[4 + i] * xv[1].y +
                               wd1[8 + i] * xv[2].y + wd1[12 + i] * xv[3].y;
    }
    __syncthreads();

    int ca = lane, cb = lane + 32;
    float acca[4] = {0, 0, 0, 0};
    float accb[4] = {0, 0, 0, 0};
    #pragma unroll
    for (int f0 = 0; f0 < 64; f0 += 4) {
        float4 h0 = *(const float4*)&h1s[warp][0][f0];
        float4 h1 = *(const float4*)&h1s[warp][1][f0];
        float4 h2 = *(const float4*)&h1s[warp][2][f0];
        float4 h3 = *(const float4*)&h1s[warp][3][f0];
        const float* wa = &w2s[ca * 65 + f0];
        const float* wb = &w2s[cb * 65 + f0];
        float wa0 = wa[0], wa1 = wa[1], wa2 = wa[2], wa3 = wa[3];
        float wb0 = wb[0], wb1 = wb[1], wb2 = wb[2], wb3 = wb[3];
        acca[0] += h0.x * wa0 + h0.y * wa1 + h0.z * wa2 + h0.w * wa3;
        acca[1] += h1.x * wa0 + h1.y * wa1 + h1.z * wa2 + h1.w * wa3;
        acca[2] += h2.x * wa0 + h2.y * wa1 + h2.z * wa2 + h2.w * wa3;
        acca[3] += h3.x * wa0 + h3.y * wa1 + h3.z * wa2 + h3.w * wa3;
        accb[0] += h0.x * wb0 + h0.y * wb1 + h0.z * wb2 + h0.w * wb3;
        accb[1] += h1.x * wb0 + h1.y * wb1 + h1.z * wb2 + h1.w * wb3;
        accb[2] += h2.x * wb0 + h2.y * wb1 + h2.z * wb2 + h2.w * wb3;
        accb[3] += h3.x * wb0 + h3.y * wb1 + h3.z * wb2 + h3.w * wb3;
    }
    #pragma unroll
    for (int k = 0; k < 4; k++) {
        Hout[n * 256 + k * 64 + ca] = acca[k];
        Hout[n * 256 + k * 64 + cb] = accb[k];
    }
}

// ---------------- gather: 5 LDG per incidence, deferred butterfly --------
__device__ __forceinline__ void proc_inc2(int idx, const float* __restrict__ Hin,
                                          int g, int cl, float part[4][4])
{
    int2 v = __ldg(&g_incid[idx]);
    int e = v.x >> 1, role = v.x & 1;
    int other = v.y;
    const float* qb = &g_Q[(size_t)e * 32 + (role ? 0 : 16)];
    const float* hb = &Hin[(size_t)other * 256 + cl * 4];

    #pragma unroll
    for (int jj = 0; jj < 2; jj++) {
        int j = g + jj * 2;
        float4 qv = *(const float4*)&qb[j * 4];
        float4 hv = *(const float4*)&hb[j * 64];
        part[0][0] += qv.x * hv.x; part[0][1] += qv.x * hv.y;
        part[0][2] += qv.x * hv.z; part[0][3] += qv.x * hv.w;
        part[1][0] += qv.y * hv.x; part[1][1] += qv.y * hv.y;
        part[1][2] += qv.y * hv.z; part[1][3] += qv.y * hv.w;
        part[2][0] += qv.z * hv.x; part[2][1] += qv.z * hv.y;
        part[2][2] += qv.z * hv.z; part[2][3] += qv.z * hv.w;
        part[3][0] += qv.w * hv.x; part[3][1] += qv.w * hv.y;
        part[3][2] += qv.w * hv.z; part[3][3] += qv.w * hv.w;
    }
}

__global__ __launch_bounds__(256)
void gather_kernel(const float* __restrict__ Hin, int nbase)
{
    __shared__ float red[4][32][16];
    int warp = threadIdx.x >> 5, lane = threadIdx.x & 31;
    int slot = warp >> 1, w2 = warp & 1;
    int n = nbase + blockIdx.x * 4 + slot;
    int beg = g_off[n], endi = g_off[n + 1];
    int cnt = endi - beg;
    int mid = beg + ((cnt + 1) >> 1);
    int lo = w2 ? mid : beg;
    int hi = w2 ? endi : mid;
    int g = lane >> 4, cl = lane & 15;

    float part[4][4] = {};

    int idx = lo;
    for (; idx + 1 < hi; idx += 2) {
        proc_inc2(idx,     Hin, g, cl, part);
        proc_inc2(idx + 1, Hin, g, cl, part);
    }
    if (idx < hi) proc_inc2(idx, Hin, g, cl, part);

    if (w2) {
        #pragma unroll
        for (int i = 0; i < 4; i++)
            #pragma unroll
            for (int c = 0; c < 4; c++)
                red[slot][lane][i * 4 + c] = part[i][c];
    }
    __syncthreads();
    if (!w2) {
        #pragma unroll
        for (int i = 0; i < 4; i++)
            #pragma unroll
            for (int c = 0; c < 4; c++)
                part[i][c] += red[slot][lane][i * 4 + c];

        const float* db = &g_zs.D[n * 16];
        const float* hb = &Hin[(size_t)n * 256 + cl * 4];
        float lh[4][4];
        {
            float4 qv0 = *(const float4*)&db[g * 4];
            float4 hv0 = *(const float4*)&hb[g * 64];
            float4 qv1 = *(const float4*)&db[(g + 2) * 4];
            float4 hv1 = *(const float4*)&hb[(g + 2) * 64];
            #pragma unroll
            for (int i = 0; i < 4; i++) {
                float qi0 = (i == 0 ? qv0.x : i == 1 ? qv0.y : i == 2 ? qv0.z : qv0.w);
                float qi1 = (i == 0 ? qv1.x : i == 1 ? qv1.y : i == 2 ? qv1.z : qv1.w);
                lh[i][0] = qi0 * hv0.x + qi1 * hv1.x - part[i][0];
                lh[i][1] = qi0 * hv0.y + qi1 * hv1.y - part[i][1];
                lh[i][2] = qi0 * hv0.z + qi1 * hv1.z - part[i][2];
                lh[i][3] = qi0 * hv0.w + qi1 * hv1.w - part[i][3];
            }
        }
        #pragma unroll
        for (int i = 0; i < 4; i++)
            #pragma unroll
            for (int c = 0; c < 4; c++)
                lh[i][c] += __shfl_xor_sync(0xffffffffu, lh[i][c], 16);

        #pragma unroll
        for (int r = 0; r < 2; r++) {
            int i = g * 2 + r;
            float* xp = &g_h[(size_t)n * 256 + i * 64 + cl * 4];
            float4 xv = *(const float4*)xp;
            xv.x -= fmaxf(lh[i][0], 0.f);
            xv.y -= fmaxf(lh[i][1], 0.f);
            xv.z -= fmaxf(lh[i][2], 0.f);
            xv.w -= fmaxf(lh[i][3], 0.f);
            *(float4*)xp = xv;
        }
    }
}

// ---------------- launch (stream-forked DAG + pipelined tail) ------------
static cudaStream_t s_s1, s_s2;
static cudaEvent_t  s_evRoot, s_evG1b, s_evWc, s_evMs, s_evComb, s_evHc0, s_evFill;
static cudaEvent_t  s_evGA, s_evHA, s_evG1A, s_evOutA;
static bool s_init = false;

extern "C" void kernel_launch(void* const* d_in, const int* in_sizes, int n_in,
                              void* d_out, int out_size)
{
    const float* x    = (const float*)d_in[0];
    const int*   ei   = (const int*)  d_in[1];
    const float* Win1 = (const float*)d_in[2];
    const float* bin1 = (const float*)d_in[3];
    const float* Win2 = (const float*)d_in[4];
    const float* bin2 = (const float*)d_in[5];
    const float* Wm1  = (const float*)d_in[6];
    const float* bm1  = (const float*)d_in[7];
    const float* Wm2  = (const float*)d_in[8];
    const float* bm2  = (const float*)d_in[9];
    const float* Wd1  = (const float*)d_in[10];
    const float* Wd2  = (const float*)d_in[11];
    const float* Wo1  = (const float*)d_in[12];
    const float* bo1  = (const float*)d_in[13];
    const float* Wo2  = (const float*)d_in[14];
    const float* bo2  = (const float*)d_in[15];
    float* out = (float*)d_out;

    if (!s_init) {
        cudaStreamCreateWithFlags(&s_s1, cudaStreamNonBlocking);
        cudaStreamCreateWithFlags(&s_s2, cudaStreamNonBlocking);
        cudaEventCreateWithFlags(&s_evRoot, cudaEventDisableTiming);
        cudaEventCreateWithFlags(&s_evG1b,  cudaEventDisableTiming);
        cudaEventCreateWithFlags(&s_evWc,   cudaEventDisableTiming);
        cudaEventCreateWithFlags(&s_evMs,   cudaEventDisableTiming);
        cudaEventCreateWithFlags(&s_evComb, cudaEventDisableTiming);
        cudaEventCreateWithFlags(&s_evHc0,  cudaEventDisableTiming);
        cudaEventCreateWithFlags(&s_evFill, cudaEventDisableTiming);
        cudaEventCreateWithFlags(&s_evGA,   cudaEventDisableTiming);
        cudaEventCreateWithFlags(&s_evHA,   cudaEventDisableTiming);
        cudaEventCreateWithFlags(&s_evG1A,  cudaEventDisableTiming);
        cudaEventCreateWithFlags(&s_evOutA, cudaEventDisableTiming);
        s_init = true;
    }

    void *p_zs, *p_h, *p_h1, *p_p0, *p_p1, *p_AB, *p_Wc, *p_bc, *p_H, *p_H2;
    cudaGetSymbolAddress(&p_zs, g_zs);
    cudaGetSymbolAddress(&p_h,  g_h);
    cudaGetSymbolAddress(&p_h1, g_h1);
    cudaGetSymbolAddress(&p_p0, g_p0);
    cudaGetSymbolAddress(&p_p1, g_p1);
    cudaGetSymbolAddress(&p_AB, g_AB);
    cudaGetSymbolAddress(&p_Wc, g_Wc);
    cudaGetSymbolAddress(&p_bc, g_bc);
    cudaGetSymbolAddress(&p_H,  g_H);
    cudaGetSymbolAddress(&p_H2, g_H2);
    float* h   = (float*)p_h;
    float* h1  = (float*)p_h1;
    float* P0  = (float*)p_p0;
    float* P1  = (float*)p_p1;
    float* AB  = (float*)p_AB;
    float* Wc  = (float*)p_Wc;
    float* bc  = (float*)p_bc;
    float* H0  = (float*)p_H;
    float* H1b = (float*)p_H2;

    const int MB = (N_NODES + 127) / 128;  // 157

    // ---- fork side streams off the capture-origin stream (0) ----
    cudaEventRecord(s_evRoot, 0);
    cudaStreamWaitEvent(s_s1, s_evRoot, 0);
    cudaStreamWaitEvent(s_s2, s_evRoot, 0);

    // ---- s2: weights-combine + CSR chain ----
    wc_kernel<<<128, 256, 0, s_s2>>>(Wm1, Win2, bin2);
    cudaEventRecord(s_evWc, s_s2);
    cudaMemsetAsync(p_zs, 0, sizeof(ZS), s_s2);
    cudaEventRecord(s_evMs, s_s2);
    count_kernel<<<(N_EDGES + 255) / 256, 256, 0, s_s2>>>(ei);
    scan_kernel<<<1, 1024, 0, s_s2>>>();
    fill_kernel<<<(N_EDGES + 255) / 256, 256, 0, s_s2>>>(ei);
    cudaEventRecord(s_evFill, s_s2);

    // ---- s1: second split-K half of input MLP ----
    sgemm128<false><<<dim3(1, MB), 256, 0, s_s1>>>(x + 256, Win1 + 256, nullptr, P1,
                                                   N_NODES, 64, 244, IN_DIM, IN_DIM);
    cudaEventRecord(s_evG1b, s_s1);

    // ---- stream 0: critical path to edge ----
    sgemm128<false><<<dim3(1, MB), 256>>>(x, Win1, nullptr, P0,
                                          N_NODES, 64, 256, IN_DIM, IN_DIM);
    cudaStreamWaitEvent(0, s_evG1b, 0);
    combine_kernel<<<(N_NODES * 64 / 4 + 255) / 256, 256>>>(bin1);
    cudaEventRecord(s_evComb, 0);
    cudaStreamWaitEvent(0, s_evWc, 0);
    sgemm128<false><<<dim3(2, MB), 256>>>(h1, Wc, bc, AB, N_NODES, 128, 64, 64, 64);
    cudaStreamWaitEvent(0, s_evMs, 0);
    edge_kernel<<<N_EDGES / 160, 256>>>(ei, Wm2, bm1, bm2);

    // ---- s1: h = h1@Win2^T + bin2; hcomp layer 0 -> H0 ----
    cudaStreamWaitEvent(s_s1, s_evComb, 0);
    sgemm128<false><<<dim3(4, MB), 256, 0, s_s1>>>(h1, Win2, bin2, h,
                                                   N_NODES, 256, 64, 64, 64);
    hcomp_kernel<<<N_NODES / 8, 256, 0, s_s1>>>(Wd1, Wd2, 0, H0, 0);
    cudaEventRecord(s_evHc0, s_s1);

    // ---- join; pipelined tail (A = nodes 0..9999, B = 10000..19999) ----
    cudaStreamWaitEvent(0, s_evFill, 0);
    cudaStreamWaitEvent(0, s_evHc0, 0);

    gather_kernel<<<2500, 256>>>(H0, 0);                       // gather0_A
    cudaEventRecord(s_evGA, 0);
    gather_kernel<<<2500, 256>>>(H0, 10000);                   // gather0_B
    // s1: hcomp1_A in parallel with gather0_B (writes H2, disjoint from H0)
    cudaStreamWaitEvent(s_s1, s_evGA, 0);
    hcomp_kernel<<<1250, 256, 0, s_s1>>>(Wd1, Wd2, 1, H1b, 0); // hcomp1_A
    cudaEventRecord(s_evHA, s_s1);
    // stream 0: hcomp1_B after gather0_B
    hcomp_kernel<<<1250, 256>>>(Wd1, Wd2, 1, H1b, 10000);      // hcomp1_B
    cudaStreamWaitEvent(0, s_evHA, 0);

    gather_kernel<<<2500, 256>>>(H1b, 0);                      // gather1_A
    cudaEventRecord(s_evG1A, 0);
    gather_kernel<<<2500, 256>>>(H1b, 10000);                  // gather1_B
    // s1: outmlp_A (rows 0..9983) in parallel with gather1_B
    cudaStreamWaitEvent(s_s1, s_evG1A, 0);
    outmlp_kernel<<<78, 256, 0, s_s1>>>(h, Wo1, bo1, Wo2, bo2, out, 0);
    cudaEventRecord(s_evOutA, s_s1);
    // stream 0: outmlp_B (rows 9984..19999) after gather1_B
    outmlp_kernel<<<MB - 78, 256>>>(h, Wo1, bo1, Wo2, bo2, out, 78);
    cudaStreamWaitEvent(0, s_evOutA, 0);   // join s1 back before capture end
}

// round 16
// speedup vs baseline: 1.0351x; 1.0351x over previous
#include <cuda_runtime.h>
#include <cuda_bf16.h>

#define N_NODES 20000
#define N_EDGES 200000
#define IN_DIM  500
#define HID     256
#define OUT_DIM 16
#define MHD     64

// ---------------- device scratch (static, no allocations) ----------------
struct ZS {                     // zeroed by ONE memset each launch
    int   cnt[N_NODES];
    float D[N_NODES * 16];      // per-node sum of P (src) + S (dst); symmetric
};
__device__ ZS    g_zs;
__device__ float g_h  [N_NODES * HID];     // h, then xb (updated in place)
__device__ float g_h1 [N_NODES * MHD];     // MLP intermediates
__device__ float g_p0 [N_NODES * MHD];     // split-K partials for input MLP
__device__ float g_p1 [N_NODES * MHD];
__device__ float g_AB [N_NODES * 2 * MHD]; // [N][128]: A | B
__device__ float g_Wc [2 * MHD * MHD];     // combined (Wab @ Win2) -> [128][64]
__device__ float g_bc [2 * MHD];           // combined bias Wab @ bin2
__device__ float g_Q  [(size_t)N_EDGES * 32]; // per edge: Q row-major, Q^T row-major
__device__ float g_H  [N_NODES * HID];     // diffusion operand H per layer
__device__ int   g_off[N_NODES + 1];
__device__ int   g_cur[N_NODES];
__device__ int2  g_incid[2 * N_EDGES];     // {(e<<1)|role, other}

// ---------------- SGEMM: C = act(A[M,K](lda) @ W[N,K](ldw)^T + b) --------
template<bool RELU>
__global__ __launch_bounds__(256, 2)
void sgemm128(const float* __restrict__ A, const float* __restrict__ W,
              const float* __restrict__ bias, float* __restrict__ C,
              int M, int N, int K, int lda, int ldw)
{
    __shared__ float As[16][132];
    __shared__ float Ws[16][68];

    int tid = threadIdx.x;
    int tx = tid & 15, ty = tid >> 4;
    int row0 = blockIdx.y * 128, col0 = blockIdx.x * 64;

    int arow = tid >> 1;
    int akb  = (tid & 1) * 8;
    int wcol = tid & 63;
    int wkb  = (tid >> 6) * 4;

    int gr = row0 + arow;
    int gc = col0 + wcol;
    const float* Arow = A + (size_t)(gr < M ? gr : 0) * lda;
    const float* Wrow = W + (size_t)(gc < N ? gc : 0) * ldw;
    bool rok = gr < M;
    bool cok = gc < N;

    float acc[8][4] = {};
    float ra[8], rw[4];

    #pragma unroll
    for (int u = 0; u < 8; u++) {
        int k = akb + u;
        ra[u] = (rok && k < K) ? Arow[k] : 0.f;
    }
    #pragma unroll
    for (int u = 0; u < 4; u++) {
        int k = wkb + u;
        rw[u] = (cok && k < K) ? Wrow[k] : 0.f;
    }

    for (int k0 = 0; k0 < K; k0 += 16) {
        #pragma unroll
        for (int u = 0; u < 8; u++) As[akb + u][arow] = ra[u];
        #pragma unroll
        for (int u = 0; u < 4; u++) Ws[wkb + u][wcol] = rw[u];
        __syncthreads();

        int kn = k0 + 16;
        if (kn < K) {
            #pragma unroll
            for (int u = 0; u < 8; u++) {
                int k = kn + akb + u;
                ra[u] = (rok && k < K) ? Arow[k] : 0.f;
            }
            #pragma unroll
            for (int u = 0; u < 4; u++) {
                int k = kn + wkb + u;
                rw[u] = (cok && k < K) ? Wrow[k] : 0.f;
            }
        }

        #pragma unroll
        for (int kk = 0; kk < 16; kk++) {
            float4 a0 = *(const float4*)&As[kk][ty * 8];
            float4 a1 = *(const float4*)&As[kk][ty * 8 + 4];
            float4 b0 = *(const float4*)&Ws[kk][tx * 4];
            float a[8] = {a0.x, a0.y, a0.z, a0.w, a1.x, a1.y, a1.z, a1.w};
            float b[4] = {b0.x, b0.y, b0.z, b0.w};
            #pragma unroll
            for (int i = 0; i < 8; i++)
                #pragma unroll
                for (int j = 0; j < 4; j++)
                    acc[i][j] += a[i] * b[j];
        }
        __syncthreads();
    }

    #pragma unroll
    for (int i = 0; i < 8; i++) {
        int r = row0 + ty * 8 + i;
        if (r >= M) continue;
        #pragma unroll
        for (int j = 0; j < 4; j++) {
            int c = col0 + tx * 4 + j;
            if (c >= N) continue;
            float v = acc[i][j] + (bias ? bias[c] : 0.f);
            if (RELU) v = fmaxf(v, 0.f);
            C[(size_t)r * N + c] = v;
        }
    }
}

// ---------------- fused output MLP: out = relu(xb@Wo1^T+bo1)@Wo2^T+bo2 ---
__global__ __launch_bounds__(256, 2)
void outmlp_kernel(const float* __restrict__ A,  const float* __restrict__ W1,
                   const float* __restrict__ b1v, const float* __restrict__ W2,
                   const float* __restrict__ b2v, float* __restrict__ C)
{
    __shared__ float buf[128 * 68];
    __shared__ float W2t[64 * 16];
    float (*As)[132] = (float(*)[132])buf;
    float (*Ws)[68]  = (float(*)[68])(buf + 16 * 132);

    const int M = N_NODES, K = 256;
    int tid = threadIdx.x;
    for (int i = tid; i < 1024; i += 256)
        W2t[(i & 63) * 16 + (i >> 6)] = W2[i];

    int tx = tid & 15, ty = tid >> 4;
    int row0 = blockIdx.x * 128;
    int arow = tid >> 1;
    int akb  = (tid & 1) * 8;
    int wcol = tid & 63;
    int wkb  = (tid >> 6) * 4;

    int gr = row0 + arow;
    const float* Arow = A + (size_t)(gr < M ? gr : 0) * 256;
    const float* Wrow = W1 + (size_t)wcol * 256;
    bool rok = gr < M;

    float acc[8][4] = {};
    float ra[8], rw[4];
    #pragma unroll
    for (int u = 0; u < 8; u++) ra[u] = rok ? Arow[akb + u] : 0.f;
    #pragma unroll
    for (int u = 0; u < 4; u++) rw[u] = Wrow[wkb + u];

    for (int k0 = 0; k0 < K; k0 += 16) {
        #pragma unroll
        for (int u = 0; u < 8; u++) As[akb + u][arow] = ra[u];
        #pragma unroll
        for (int u = 0; u < 4; u++) Ws[wkb + u][wcol] = rw[u];
        __syncthreads();

        int kn = k0 + 16;
        if (kn < K) {
            #pragma unroll
            for (int u = 0; u < 8; u++) ra[u] = rok ? Arow[kn + akb + u] : 0.f;
            #pragma unroll
            for (int u = 0; u < 4; u++) rw[u] = Wrow[kn + wkb + u];
        }

        #pragma unroll
        for (int kk = 0; kk < 16; kk++) {
            float4 a0 = *(const float4*)&As[kk][ty * 8];
            float4 a1 = *(const float4*)&As[kk][ty * 8 + 4];
            float4 b0 = *(const float4*)&Ws[kk][tx * 4];
            float a[8] = {a0.x, a0.y, a0.z, a0.w, a1.x, a1.y, a1.z, a1.w};
            float b[4] = {b0.x, b0.y, b0.z, b0.w};
            #pragma unroll
            for (int i = 0; i < 8; i++)
                #pragma unroll
                for (int j = 0; j < 4; j++)
                    acc[i][j] += a[i] * b[j];
        }
        __syncthreads();
    }

    float* h1s = buf;
    #pragma unroll
    for (int i = 0; i < 8; i++) {
        int r = ty * 8 + i;
        #pragma unroll
        for (int j = 0; j < 4; j++) {
            int c = tx * 4 + j;
            h1s[r * 68 + c] = fmaxf(acc[i][j] + b1v[c], 0.f);
        }
    }
    __syncthreads();

    int row = tid >> 1, ch = tid & 1;
    float a8[8] = {};
    #pragma unroll 8
    for (int k = 0; k < 64; k++) {
        float hv = h1s[row * 68 + k];
        float4 wA = *(const float4*)&W2t[k * 16 + ch * 8];
        float4 wB = *(const float4*)&W2t[k * 16 + ch * 8 + 4];
        a8[0] += hv * wA.x; a8[1] += hv * wA.y;
        a8[2] += hv * wA.z; a8[3] += hv * wA.w;
        a8[4] += hv * wB.x; a8[5] += hv * wB.y;
        a8[6] += hv * wB.z; a8[7] += hv * wB.w;
    }
    int gr2 = row0 + row;
    if (gr2 < M) {
        float4 bA = *(const float4*)&b2v[ch * 8];
        float4 bB = *(const float4*)&b2v[ch * 8 + 4];
        float4 oA = make_float4(a8[0] + bA.x, a8[1] + bA.y, a8[2] + bA.z, a8[3] + bA.w);
        float4 oB = make_float4(a8[4] + bB.x, a8[5] + bB.y, a8[6] + bB.z, a8[7] + bB.w);
        *(float4*)&C[(size_t)gr2 * 16 + ch * 8]     = oA;
        *(float4*)&C[(size_t)gr2 * 16 + ch * 8 + 4] = oB;
    }
}

// ---------------- combine split-K partials: h1 = relu(p0+p1+bias) --------
__global__ __launch_bounds__(256)
void combine_kernel(const float* __restrict__ bias)
{
    int i = blockIdx.x * 256 + threadIdx.x;
    float4 a = ((const float4*)g_p0)[i];
    float4 b = ((const float4*)g_p1)[i];
    float4 bs = *(const float4*)&bias[(i * 4) & 63];
    float4 r;
    r.x = fmaxf(a.x + b.x + bs.x, 0.f);
    r.y = fmaxf(a.y + b.y + bs.y, 0.f);
    r.z = fmaxf(a.z + b.z + bs.z, 0.f);
    r.w = fmaxf(a.w + b.w + bs.w, 0.f);
    ((float4*)g_h1)[i] = r;
}

// ---------------- CSR build ----------------
__global__ void count_kernel(const int* __restrict__ ei) {
    int e = blockIdx.x * 256 + threadIdx.x;
    if (e < N_EDGES) {
        atomicAdd(&g_zs.cnt[ei[e]], 1);
        atomicAdd(&g_zs.cnt[ei[N_EDGES + e]], 1);
    }
}

__global__ void scan_kernel() {
    const int CH = (N_NODES + 1023) / 1024;  // 20
    __shared__ int ssum[1024];
    int tid = threadIdx.x;
    int begin = tid * CH;
    int endi = begin + CH; if (endi > N_NODES) endi = N_NODES;
    int s = 0;
    for (int i = begin; i < endi; i++) s += g_zs.cnt[i];
    ssum[tid] = s;
    __syncthreads();
    for (int off = 1; off < 1024; off <<= 1) {
        int v = 0;
        if (tid >= off) v = ssum[tid - off];
        __syncthreads();
        ssum[tid] += v;
        __syncthreads();
    }
    int run = ssum[tid] - s;
    for (int i = begin; i < endi; i++) {
        g_off[i] = run;
        g_cur[i] = run;
        run += g_zs.cnt[i];
    }
    if (tid == 1023) g_off[N_NODES] = ssum[1023];
}

__global__ void fill_kernel(const int* __restrict__ ei) {
    int e = blockIdx.x * 256 + threadIdx.x;
    if (e < N_EDGES) {
        int s = ei[e], d = ei[N_EDGES + e];
        int p = atomicAdd(&g_cur[s], 1);
        g_incid[p] = make_int2(e << 1, d);
        int p2 = atomicAdd(&g_cur[d], 1);
        g_incid[p2] = make_int2((e << 1) | 1, s);
    }
}

// ---------------- combined weights: Wc = Wab @ Win2, bc = Wab @ bin2 -----
__global__ __launch_bounds__(256)
void wc_kernel(const float* __restrict__ Wm1,
               const float* __restrict__ Win2,
               const float* __restrict__ bin2)
{
    __shared__ float part[256];
    __shared__ float bpart[64];
    int i = blockIdx.x;
    const float* wrow = (i < 64) ? &Wm1[i * 512] : &Wm1[(i - 64) * 512 + 256];
    int t = threadIdx.x;
    int mh = t & 63, kq = t >> 6;
    float s = 0.f;
    #pragma unroll 16
    for (int k = kq * 64; k < kq * 64 + 64; k++)
        s += wrow[k] * Win2[k * 64 + mh];
    part[t] = s;
    if (kq == 0) {
        float b = 0.f;
        #pragma unroll
        for (int k = mh * 4; k < mh * 4 + 4; k++) b += wrow[k] * bin2[k];
        bpart[mh] = b;
    }
    __syncthreads();
    if (kq == 0)
        g_Wc[i * 64 + mh] = part[mh] + part[64 + mh] + part[128 + mh] + part[192 + mh];
    if (t == 0) {
        float bb = 0.f;
        #pragma unroll
        for (int k = 0; k < 64; k++) bb += bpart[k];
        g_bc[i] = bb;
    }
}

// ---------------- per-edge v4: weights-in-regs, 20 edges/warp, shfl fsft -
__global__ __launch_bounds__(256, 2)
void edge_kernel(const int* __restrict__ ei, const float* __restrict__ Wm2,
                 const float* __restrict__ bm1, const float* __restrict__ bm2)
{
    __shared__ float W4s[1024];
    __shared__ float sbuf[8 * 128];
    int tid = threadIdx.x;
    for (int idx = tid; idx < 1024; idx += 256) {
        int o = idx >> 6, k = idx & 63;
        W4s[((k >> 2) << 6) + (o << 2) + (k & 3)] = Wm2[idx];
    }
    __syncthreads();

    int warp = tid >> 5, lane = tid & 31;
    int o = lane & 15;
    float* sw = &sbuf[warp * 128];
    int k0 = lane * 2;

    float4 wreg[16];
    #pragma unroll
    for (int kc = 0; kc < 16; kc++)
        wreg[kc] = *(const float4*)&W4s[kc * 64 + o * 4];
    float2 b1 = *(const float2*)&bm1[k0];
    float bm2o = __ldg(&bm2[o]);
    int i = o >> 2, j = o & 3;

    const int EPW = 20;
    int e0 = (blockIdx.x * 8 + warp) * EPW;  // grid 1250, exact

    int sA = ei[e0], dA = ei[N_EDGES + e0];
    float2 AsA = *(const float2*)&g_AB[sA * 128 + k0];
    float2 BdA = *(const float2*)&g_AB[dA * 128 + 64 + k0];
    float2 AdA = *(const float2*)&g_AB[dA * 128 + k0];
    float2 BsA = *(const float2*)&g_AB[sA * 128 + 64 + k0];

    #pragma unroll 4
    for (int t = 0; t < EPW; t++) {
        int e = e0 + t;
        int sB = 0, dB = 0;
        float2 AsB, BdB, AdB, BsB;
        if (t < EPW - 1) {
            sB = ei[e + 1]; dB = ei[N_EDGES + e + 1];
            AsB = *(const float2*)&g_AB[sB * 128 + k0];
            BdB = *(const float2*)&g_AB[dB * 128 + 64 + k0];
            AdB = *(const float2*)&g_AB[dB * 128 + k0];
            BsB = *(const float2*)&g_AB[sB * 128 + 64 + k0];
        }

        float2 t1v = make_float2(fmaxf(AsA.x + BdA.x + b1.x, 0.f),
                                 fmaxf(AsA.y + BdA.y + b1.y, 0.f));
        float2 t2v = make_float2(fmaxf(AdA.x + BsA.x + b1.x, 0.f),
                                 fmaxf(AdA.y + BsA.y + b1.y, 0.f));
        __syncwarp();
        *(float2*)&sw[k0]      = t1v;
        *(float2*)&sw[64 + k0] = t2v;
        __syncwarp();

        const float* tv = sw + ((lane >> 4) << 6);
        float accf = 0.f;
        #pragma unroll
        for (int kc = 0; kc < 16; kc++) {
            float4 tval = *(const float4*)&tv[kc * 4];
            float4 w = wreg[kc];
            accf += tval.x * w.x + tval.y * w.y + tval.z * w.z + tval.w * w.w;
        }
        accf += bm2o;

        float p = 0.f, q = 0.f, ss = 0.f;
        #pragma unroll
        for (int m = 0; m < 4; m++) {
            float fsi = __shfl_sync(0xffffffffu, accf, m * 4 + i);
            float fsj = __shfl_sync(0xffffffffu, accf, m * 4 + j);
            float fti = __shfl_sync(0xffffffffu, accf, 16 + m * 4 + i);
            float ftj = __shfl_sync(0xffffffffu, accf, 16 + m * 4 + j);
            p  += fsi * fsj;
            q  += fsi * ftj;
            ss += fti * ftj;
        }
        if (lane < 16) {
            float* qb = &g_Q[(size_t)e * 32];
            qb[lane] = q;
            qb[16 + j * 4 + i] = q;
            atomicAdd(&g_zs.D[sA * 16 + lane], p);
            atomicAdd(&g_zs.D[dA * 16 + lane], ss);
        }

        sA = sB; dA = dB;
        AsA = AsB; BdA = BdB; AdA = AdB; BsA = BsB;
    }
}

// ---------------- per-node H = (Wd1^T @ xb) @ Wd2^T ----------------------
__global__ __launch_bounds__(256)
void hcomp_kernel(const float* __restrict__ Wd1, const float* __restrict__ Wd2,
                  int layer, int nbase)
{
    __shared__ float w2s[64 * 65];
    __shared__ float h1s[8][4][64];
    int tid = threadIdx.x;
    for (int idx = tid; idx < 4096; idx += 256) {
        int g = idx >> 6, f = idx & 63;
        w2s[g * 65 + f] = Wd2[layer * 4096 + idx];
    }
    float wd1[16];
    #pragma unroll
    for (int i = 0; i < 16; i++) wd1[i] = __ldg(&Wd1[layer * 16 + i]);

    int warp = tid >> 5, lane = tid & 31;
    int n = nbase + blockIdx.x * 8 + warp;
    int c0 = lane * 2;
    float2 xv[4];
    #pragma unroll
    for (int j = 0; j < 4; j++)
        xv[j] = *(const float2*)&g_h[n * 256 + j * 64 + c0];
    #pragma unroll
    for (int i = 0; i < 4; i++) {
        h1s[warp][i][c0]     = wd1[i] * xv[0].x + wd1[4 + i] * xv[1].x +
                               wd1[8 + i] * xv[2].x + wd1[12 + i] * xv[3].x;
        h1s[warp][i][c0 + 1] = wd1[i] * xv[0].y + wd1[4 + i] * xv[1].y +
                               wd1[8 + i] * xv[2].y + wd1[12 + i] * xv[3].y;
    }
    __syncthreads();

    int ca = lane, cb = lane + 32;
    float acca[4] = {0, 0, 0, 0};
    float accb[4] = {0, 0, 0, 0};
    #pragma unroll
    for (int f0 = 0; f0 < 64; f0 += 4) {
        float4 h0 = *(const float4*)&h1s[warp][0][f0];
        float4 h1 = *(const float4*)&h1s[warp][1][f0];
        float4 h2 = *(const float4*)&h1s[warp][2][f0];
        float4 h3 = *(const float4*)&h1s[warp][3][f0];
        const float* wa = &w2s[ca * 65 + f0];
        const float* wb = &w2s[cb * 65 + f0];
        float wa0 = wa[0], wa1 = wa[1], wa2 = wa[2], wa3 = wa[3];
        float wb0 = wb[0], wb1 = wb[1], wb2 = wb[2], wb3 = wb[3];
        acca[0] += h0.x * wa0 + h0.y * wa1 + h0.z * wa2 + h0.w * wa3;
        acca[1] += h1.x * wa0 + h1.y * wa1 + h1.z * wa2 + h1.w * wa3;
        acca[2] += h2.x * wa0 + h2.y * wa1 + h2.z * wa2 + h2.w * wa3;
        acca[3] += h3.x * wa0 + h3.y * wa1 + h3.z * wa2 + h3.w * wa3;
        accb[0] += h0.x * wb0 + h0.y * wb1 + h0.z * wb2 + h0.w * wb3;
        accb[1] += h1.x * wb0 + h1.y * wb1 + h1.z * wb2 + h1.w * wb3;
        accb[2] += h2.x * wb0 + h2.y * wb1 + h2.z * wb2 + h2.w * wb3;
        accb[3] += h3.x * wb0 + h3.y * wb1 + h3.z * wb2 + h3.w * wb3;
    }
    #pragma unroll
    for (int k = 0; k < 4; k++) {
        g_H[n * 256 + k * 64 + ca] = acca[k];
        g_H[n * 256 + k * 64 + cb] = accb[k];
    }
}

// ---------------- gather: 5 LDG per incidence, deferred butterfly --------
__device__ __forceinline__ void proc_inc2(int idx, int g, int cl, float part[4][4])
{
    int2 v = __ldg(&g_incid[idx]);
    int e = v.x >> 1, role = v.x & 1;
    int other = v.y;
    const float* qb = &g_Q[(size_t)e * 32 + (role ? 0 : 16)];
    const float* hb = &g_H[(size_t)other * 256 + cl * 4];

    #pragma unroll
    for (int jj = 0; jj < 2; jj++) {
        int j = g + jj * 2;
        float4 qv = *(const float4*)&qb[j * 4];
        float4 hv = *(const float4*)&hb[j * 64];
        part[0][0] += qv.x * hv.x; part[0][1] += qv.x * hv.y;
        part[0][2] += qv.x * hv.z; part[0][3] += qv.x * hv.w;
        part[1][0] += qv.y * hv.x; part[1][1] += qv.y * hv.y;
        part[1][2] += qv.y * hv.z; part[1][3] += qv.y * hv.w;
        part[2][0] += qv.z * hv.x; part[2][1] += qv.z * hv.y;
        part[2][2] += qv.z * hv.z; part[2][3] += qv.z * hv.w;
        part[3][0] += qv.w * hv.x; part[3][1] += qv.w * hv.y;
        part[3][2] += qv.w * hv.z; part[3][3] += qv.w * hv.w;
    }
}

__global__ __launch_bounds__(256)
void gather_kernel()
{
    __shared__ float red[4][32][16];
    int warp = threadIdx.x >> 5, lane = threadIdx.x & 31;
    int slot = warp >> 1, w2 = warp & 1;
    int n = blockIdx.x * 4 + slot;     // grid 5000, exact
    int beg = g_off[n], endi = g_off[n + 1];
    int cnt = endi - beg;
    int mid = beg + ((cnt + 1) >> 1);
    int lo = w2 ? mid : beg;
    int hi = w2 ? endi : mid;
    int g = lane >> 4, cl = lane & 15;

    float part[4][4] = {};

    int idx = lo;
    for (; idx + 1 < hi; idx += 2) {
        proc_inc2(idx,     g, cl, part);
        proc_inc2(idx + 1, g, cl, part);
    }
    if (idx < hi) proc_inc2(idx, g, cl, part);

    if (w2) {
        #pragma unroll
        for (int i = 0; i < 4; i++)
            #pragma unroll
            for (int c = 0; c < 4; c++)
                red[slot][lane][i * 4 + c] = part[i][c];
    }
    __syncthreads();
    if (!w2) {
        #pragma unroll
        for (int i = 0; i < 4; i++)
            #pragma unroll
            for (int c = 0; c < 4; c++)
                part[i][c] += red[slot][lane][i * 4 + c];

        const float* db = &g_zs.D[n * 16];
        const float* hb = &g_H[(size_t)n * 256 + cl * 4];
        float lh[4][4];
        {
            float4 qv0 = *(const float4*)&db[g * 4];
            float4 hv0 = *(const float4*)&hb[g * 64];
            float4 qv1 = *(const float4*)&db[(g + 2) * 4];
            float4 hv1 = *(const float4*)&hb[(g + 2) * 64];
            #pragma unroll
            for (int i = 0; i < 4; i++) {
                float qi0 = (i == 0 ? qv0.x : i == 1 ? qv0.y : i == 2 ? qv0.z : qv0.w);
                float qi1 = (i == 0 ? qv1.x : i == 1 ? qv1.y : i == 2 ? qv1.z : qv1.w);
                lh[i][0] = qi0 * hv0.x + qi1 * hv1.x - part[i][0];
                lh[i][1] = qi0 * hv0.y + qi1 * hv1.y - part[i][1];
                lh[i][2] = qi0 * hv0.z + qi1 * hv1.z - part[i][2];
                lh[i][3] = qi0 * hv0.w + qi1 * hv1.w - part[i][3];
            }
        }
        #pragma unroll
        for (int i = 0; i < 4; i++)
            #pragma unroll
            for (int c = 0; c < 4; c++)
                lh[i][c] += __shfl_xor_sync(0xffffffffu, lh[i][c], 16);

        #pragma unroll
        for (int r = 0; r < 2; r++) {
            int i = g * 2 + r;
            float* xp = &g_h[(size_t)n * 256 + i * 64 + cl * 4];
            float4 xv = *(const float4*)xp;
            xv.x -= fmaxf(lh[i][0], 0.f);
            xv.y -= fmaxf(lh[i][1], 0.f);
            xv.z -= fmaxf(lh[i][2], 0.f);
            xv.w -= fmaxf(lh[i][3], 0.f);
            *(float4*)xp = xv;
        }
    }
}

// ---------------- launch (stream-forked DAG) ----------------
static cudaStream_t s_s1, s_s2;
static cudaEvent_t  s_evRoot, s_evG1b, s_evWc, s_evMs, s_evComb, s_evH,
                    s_evHc0A, s_evHc0B, s_evFill;
static bool s_init = false;

extern "C" void kernel_launch(void* const* d_in, const int* in_sizes, int n_in,
                              void* d_out, int out_size)
{
    const float* x    = (const float*)d_in[0];
    const int*   ei   = (const int*)  d_in[1];
    const float* Win1 = (const float*)d_in[2];
    const float* bin1 = (const float*)d_in[3];
    const float* Win2 = (const float*)d_in[4];
    const float* bin2 = (const float*)d_in[5];
    const float* Wm1  = (const float*)d_in[6];
    const float* bm1  = (const float*)d_in[7];
    const float* Wm2  = (const float*)d_in[8];
    const float* bm2  = (const float*)d_in[9];
    const float* Wd1  = (const float*)d_in[10];
    const float* Wd2  = (const float*)d_in[11];
    const float* Wo1  = (const float*)d_in[12];
    const float* bo1  = (const float*)d_in[13];
    const float* Wo2  = (const float*)d_in[14];
    const float* bo2  = (const float*)d_in[15];
    float* out = (float*)d_out;

    if (!s_init) {
        cudaStreamCreateWithFlags(&s_s1, cudaStreamNonBlocking);
        cudaStreamCreateWithFlags(&s_s2, cudaStreamNonBlocking);
        cudaEventCreateWithFlags(&s_evRoot, cudaEventDisableTiming);
        cudaEventCreateWithFlags(&s_evG1b,  cudaEventDisableTiming);
        cudaEventCreateWithFlags(&s_evWc,   cudaEventDisableTiming);
        cudaEventCreateWithFlags(&s_evMs,   cudaEventDisableTiming);
        cudaEventCreateWithFlags(&s_evComb, cudaEventDisableTiming);
        cudaEventCreateWithFlags(&s_evH,    cudaEventDisableTiming);
        cudaEventCreateWithFlags(&s_evHc0A, cudaEventDisableTiming);
        cudaEventCreateWithFlags(&s_evHc0B, cudaEventDisableTiming);
        cudaEventCreateWithFlags(&s_evFill, cudaEventDisableTiming);
        s_init = true;
    }

    void *p_zs, *p_h, *p_h1, *p_p0, *p_p1, *p_AB, *p_Wc, *p_bc;
    cudaGetSymbolAddress(&p_zs, g_zs);
    cudaGetSymbolAddress(&p_h,  g_h);
    cudaGetSymbolAddress(&p_h1, g_h1);
    cudaGetSymbolAddress(&p_p0, g_p0);
    cudaGetSymbolAddress(&p_p1, g_p1);
    cudaGetSymbolAddress(&p_AB, g_AB);
    cudaGetSymbolAddress(&p_Wc, g_Wc);
    cudaGetSymbolAddress(&p_bc, g_bc);
    float* h   = (float*)p_h;
    float* h1  = (float*)p_h1;
    float* P0  = (float*)p_p0;
    float* P1  = (float*)p_p1;
    float* AB  = (float*)p_AB;
    float* Wc  = (float*)p_Wc;
    float* bc  = (float*)p_bc;

    const int MB = (N_NODES + 127) / 128;  // 157

    // ---- fork side streams off the capture-origin stream (0) ----
    cudaEventRecord(s_evRoot, 0);
    cudaStreamWaitEvent(s_s1, s_evRoot, 0);
    cudaStreamWaitEvent(s_s2, s_evRoot, 0);

    // ---- s2: weights-combine + CSR chain ----
    wc_kernel<<<128, 256, 0, s_s2>>>(Wm1, Win2, bin2);
    cudaEventRecord(s_evWc, s_s2);
    cudaMemsetAsync(p_zs, 0, sizeof(ZS), s_s2);
    cudaEventRecord(s_evMs, s_s2);
    count_kernel<<<(N_EDGES + 255) / 256, 256, 0, s_s2>>>(ei);
    scan_kernel<<<1, 1024, 0, s_s2>>>();
    fill_kernel<<<(N_EDGES + 255) / 256, 256, 0, s_s2>>>(ei);
    cudaEventRecord(s_evFill, s_s2);

    // ---- s1: second split-K half of input MLP ----
    sgemm128<false><<<dim3(1, MB), 256, 0, s_s1>>>(x + 256, Win1 + 256, nullptr, P1,
                                                   N_NODES, 64, 244, IN_DIM, IN_DIM);
    cudaEventRecord(s_evG1b, s_s1);

    // ---- stream 0: critical path to edge ----
    sgemm128<false><<<dim3(1, MB), 256>>>(x, Win1, nullptr, P0,
                                          N_NODES, 64, 256, IN_DIM, IN_DIM);
    cudaStreamWaitEvent(0, s_evG1b, 0);
    combine_kernel<<<(N_NODES * 64 / 4 + 255) / 256, 256>>>(bin1);
    cudaEventRecord(s_evComb, 0);
    cudaStreamWaitEvent(0, s_evWc, 0);
    sgemm128<false><<<dim3(2, MB), 256>>>(h1, Wc, bc, AB, N_NODES, 128, 64, 64, 64);
    cudaStreamWaitEvent(0, s_evMs, 0);
    edge_kernel<<<N_EDGES / 160, 256>>>(ei, Wm2, bm1, bm2);

    // ---- s1: h = h1@Win2^T + bin2; hcomp0 split A(s1)/B(s2) ----
    cudaStreamWaitEvent(s_s1, s_evComb, 0);
    sgemm128<false><<<dim3(4, MB), 256, 0, s_s1>>>(h1, Win2, bin2, h,
                                                   N_NODES, 256, 64, 64, 64);
    cudaEventRecord(s_evH, s_s1);
    hcomp_kernel<<<1250, 256, 0, s_s1>>>(Wd1, Wd2, 0, 0);       // nodes 0..9999
    cudaEventRecord(s_evHc0A, s_s1);
    cudaStreamWaitEvent(s_s2, s_evH, 0);                        // s2 idle after fill
    hcomp_kernel<<<1250, 256, 0, s_s2>>>(Wd1, Wd2, 0, 10000);   // nodes 10000..19999
    cudaEventRecord(s_evHc0B, s_s2);

    // ---- join: gather layer 0 needs edge(0) + fill(s2) + hcomp0 A&B ----
    cudaStreamWaitEvent(0, s_evFill, 0);
    cudaStreamWaitEvent(0, s_evHc0A, 0);
    cudaStreamWaitEvent(0, s_evHc0B, 0);
    gather_kernel<<<N_NODES / 4, 256>>>();
    hcomp_kernel<<<N_NODES / 8, 256>>>(Wd1, Wd2, 1, 0);
    gather_kernel<<<N_NODES / 4, 256>>>();

    // ---- fused output MLP ----
    outmlp_kernel<<<MB, 256>>>(h, Wo1, bo1, Wo2, bo2, out);
}

// round 17
// speedup vs baseline: 1.0380x; 1.0028x over previous
#include <cuda_runtime.h>
#include <cuda_bf16.h>

#define N_NODES 20000
#define N_EDGES 200000
#define IN_DIM  500
#define HID     256
#define OUT_DIM 16
#define MHD     64

// ---------------- device scratch (static, no allocations) ----------------
struct ZS {                     // zeroed by ONE memset each launch
    int   cnt[N_NODES];
    float D[N_NODES * 16];      // per-node sum of P (src) + S (dst); symmetric
};
__device__ ZS    g_zs;
__device__ float g_h  [N_NODES * HID];     // h, then xb (updated in place)
__device__ float g_h1 [N_NODES * MHD];     // MLP intermediates
__device__ float g_p0 [N_NODES * MHD];     // split-K partials for input MLP
__device__ float g_p1 [N_NODES * MHD];
__device__ float g_AB [N_NODES * 2 * MHD]; // [N][128]: A | B
__device__ float g_Wc [2 * MHD * MHD];     // combined (Wab @ Win2) -> [128][64]
__device__ float g_bc [2 * MHD];           // combined bias Wab @ bin2
__device__ float g_Q  [(size_t)N_EDGES * 32]; // per edge: Q row-major, Q^T row-major
__device__ float g_H  [N_NODES * HID];     // diffusion operand H per layer
__device__ int   g_off[N_NODES + 1];
__device__ int   g_cur[N_NODES];
__device__ int2  g_incid[2 * N_EDGES];     // {(e<<1)|role, other}

// ---------------- SGEMM: C = act(Aeff[M,K](lda) @ W[N,K](ldw)^T + b) -----
// COMB: Aeff[r][k] = relu(A[r][k] + A2[r][k] + abias[k])
template<bool RELU, bool COMB>
__global__ __launch_bounds__(256, 2)
void sgemm128(const float* __restrict__ A, const float* __restrict__ A2,
              const float* __restrict__ abias,
              const float* __restrict__ W,
              const float* __restrict__ bias, float* __restrict__ C,
              int M, int N, int K, int lda, int ldw)
{
    __shared__ float As[16][132];
    __shared__ float Ws[16][68];

    int tid = threadIdx.x;
    int tx = tid & 15, ty = tid >> 4;
    int row0 = blockIdx.y * 128, col0 = blockIdx.x * 64;

    int arow = tid >> 1;
    int akb  = (tid & 1) * 8;
    int wcol = tid & 63;
    int wkb  = (tid >> 6) * 4;

    int gr = row0 + arow;
    int gc = col0 + wcol;
    size_t aoff = (size_t)(gr < M ? gr : 0) * lda;
    const float* Arow  = A + aoff;
    const float* A2row = COMB ? (A2 + aoff) : nullptr;
    const float* Wrow = W + (size_t)(gc < N ? gc : 0) * ldw;
    bool rok = gr < M;
    bool cok = gc < N;

    float acc[8][4] = {};
    float ra[8], rw[4];

    #pragma unroll
    for (int u = 0; u < 8; u++) {
        int k = akb + u;
        float v = 0.f;
        if (rok && k < K) {
            v = Arow[k];
            if (COMB) v = fmaxf(v + A2row[k] + __ldg(&abias[k]), 0.f);
        }
        ra[u] = v;
    }
    #pragma unroll
    for (int u = 0; u < 4; u++) {
        int k = wkb + u;
        rw[u] = (cok && k < K) ? Wrow[k] : 0.f;
    }

    for (int k0 = 0; k0 < K; k0 += 16) {
        #pragma unroll
        for (int u = 0; u < 8; u++) As[akb + u][arow] = ra[u];
        #pragma unroll
        for (int u = 0; u < 4; u++) Ws[wkb + u][wcol] = rw[u];
        __syncthreads();

        int kn = k0 + 16;
        if (kn < K) {
            #pragma unroll
            for (int u = 0; u < 8; u++) {
                int k = kn + akb + u;
                float v = 0.f;
                if (rok && k < K) {
                    v = Arow[k];
                    if (COMB) v = fmaxf(v + A2row[k] + __ldg(&abias[k]), 0.f);
                }
                ra[u] = v;
            }
            #pragma unroll
            for (int u = 0; u < 4; u++) {
                int k = kn + wkb + u;
                rw[u] = (cok && k < K) ? Wrow[k] : 0.f;
            }
        }

        #pragma unroll
        for (int kk = 0; kk < 16; kk++) {
            float4 a0 = *(const float4*)&As[kk][ty * 8];
            float4 a1 = *(const float4*)&As[kk][ty * 8 + 4];
            float4 b0 = *(const float4*)&Ws[kk][tx * 4];
            float a[8] = {a0.x, a0.y, a0.z, a0.w, a1.x, a1.y, a1.z, a1.w};
            float b[4] = {b0.x, b0.y, b0.z, b0.w};
            #pragma unroll
            for (int i = 0; i < 8; i++)
                #pragma unroll
                for (int j = 0; j < 4; j++)
                    acc[i][j] += a[i] * b[j];
        }
        __syncthreads();
    }

    #pragma unroll
    for (int i = 0; i < 8; i++) {
        int r = row0 + ty * 8 + i;
        if (r >= M) continue;
        #pragma unroll
        for (int j = 0; j < 4; j++) {
            int c = col0 + tx * 4 + j;
            if (c >= N) continue;
            float v = acc[i][j] + (bias ? bias[c] : 0.f);
            if (RELU) v = fmaxf(v, 0.f);
            C[(size_t)r * N + c] = v;
        }
    }
}

// ---------------- fused output MLP: out = relu(xb@Wo1^T+bo1)@Wo2^T+bo2 ---
__global__ __launch_bounds__(256, 2)
void outmlp_kernel(const float* __restrict__ A,  const float* __restrict__ W1,
                   const float* __restrict__ b1v, const float* __restrict__ W2,
                   const float* __restrict__ b2v, float* __restrict__ C)
{
    __shared__ float buf[128 * 68];
    __shared__ float W2t[64 * 16];
    float (*As)[132] = (float(*)[132])buf;
    float (*Ws)[68]  = (float(*)[68])(buf + 16 * 132);

    const int M = N_NODES, K = 256;
    int tid = threadIdx.x;
    for (int i = tid; i < 1024; i += 256)
        W2t[(i & 63) * 16 + (i >> 6)] = W2[i];

    int tx = tid & 15, ty = tid >> 4;
    int row0 = blockIdx.x * 128;
    int arow = tid >> 1;
    int akb  = (tid & 1) * 8;
    int wcol = tid & 63;
    int wkb  = (tid >> 6) * 4;

    int gr = row0 + arow;
    const float* Arow = A + (size_t)(gr < M ? gr : 0) * 256;
    const float* Wrow = W1 + (size_t)wcol * 256;
    bool rok = gr < M;

    float acc[8][4] = {};
    float ra[8], rw[4];
    #pragma unroll
    for (int u = 0; u < 8; u++) ra[u] = rok ? Arow[akb + u] : 0.f;
    #pragma unroll
    for (int u = 0; u < 4; u++) rw[u] = Wrow[wkb + u];

    for (int k0 = 0; k0 < K; k0 += 16) {
        #pragma unroll
        for (int u = 0; u < 8; u++) As[akb + u][arow] = ra[u];
        #pragma unroll
        for (int u = 0; u < 4; u++) Ws[wkb + u][wcol] = rw[u];
        __syncthreads();

        int kn = k0 + 16;
        if (kn < K) {
            #pragma unroll
            for (int u = 0; u < 8; u++) ra[u] = rok ? Arow[kn + akb + u] : 0.f;
            #pragma unroll
            for (int u = 0; u < 4; u++) rw[u] = Wrow[kn + wkb + u];
        }

        #pragma unroll
        for (int kk = 0; kk < 16; kk++) {
            float4 a0 = *(const float4*)&As[kk][ty * 8];
            float4 a1 = *(const float4*)&As[kk][ty * 8 + 4];
            float4 b0 = *(const float4*)&Ws[kk][tx * 4];
            float a[8] = {a0.x, a0.y, a0.z, a0.w, a1.x, a1.y, a1.z, a1.w};
            float b[4] = {b0.x, b0.y, b0.z, b0.w};
            #pragma unroll
            for (int i = 0; i < 8; i++)
                #pragma unroll
                for (int j = 0; j < 4; j++)
                    acc[i][j] += a[i] * b[j];
        }
        __syncthreads();
    }

    float* h1s = buf;
    #pragma unroll
    for (int i = 0; i < 8; i++) {
        int r = ty * 8 + i;
        #pragma unroll
        for (int j = 0; j < 4; j++) {
            int c = tx * 4 + j;
            h1s[r * 68 + c] = fmaxf(acc[i][j] + b1v[c], 0.f);
        }
    }
    __syncthreads();

    int row = tid >> 1, ch = tid & 1;
    float a8[8] = {};
    #pragma unroll 8
    for (int k = 0; k < 64; k++) {
        float hv = h1s[row * 68 + k];
        float4 wA = *(const float4*)&W2t[k * 16 + ch * 8];
        float4 wB = *(const float4*)&W2t[k * 16 + ch * 8 + 4];
        a8[0] += hv * wA.x; a8[1] += hv * wA.y;
        a8[2] += hv * wA.z; a8[3] += hv * wA.w;
        a8[4] += hv * wB.x; a8[5] += hv * wB.y;
        a8[6] += hv * wB.z; a8[7] += hv * wB.w;
    }
    int gr2 = row0 + row;
    if (gr2 < M) {
        float4 bA = *(const float4*)&b2v[ch * 8];
        float4 bB = *(const float4*)&b2v[ch * 8 + 4];
        float4 oA = make_float4(a8[0] + bA.x, a8[1] + bA.y, a8[2] + bA.z, a8[3] + bA.w);
        float4 oB = make_float4(a8[4] + bB.x, a8[5] + bB.y, a8[6] + bB.z, a8[7] + bB.w);
        *(float4*)&C[(size_t)gr2 * 16 + ch * 8]     = oA;
        *(float4*)&C[(size_t)gr2 * 16 + ch * 8 + 4] = oB;
    }
}

// ---------------- combine split-K partials: h1 = relu(p0+p1+bias) --------
__global__ __launch_bounds__(256)
void combine_kernel(const float* __restrict__ bias)
{
    int i = blockIdx.x * 256 + threadIdx.x;
    float4 a = ((const float4*)g_p0)[i];
    float4 b = ((const float4*)g_p1)[i];
    float4 bs = *(const float4*)&bias[(i * 4) & 63];
    float4 r;
    r.x = fmaxf(a.x + b.x + bs.x, 0.f);
    r.y = fmaxf(a.y + b.y + bs.y, 0.f);
    r.z = fmaxf(a.z + b.z + bs.z, 0.f);
    r.w = fmaxf(a.w + b.w + bs.w, 0.f);
    ((float4*)g_h1)[i] = r;
}

// ---------------- CSR build ----------------
__global__ void count_kernel(const int* __restrict__ ei) {
    int e = blockIdx.x * 256 + threadIdx.x;
    if (e < N_EDGES) {
        atomicAdd(&g_zs.cnt[ei[e]], 1);
        atomicAdd(&g_zs.cnt[ei[N_EDGES + e]], 1);
    }
}

__global__ void scan_kernel() {
    const int CH = (N_NODES + 1023) / 1024;  // 20
    __shared__ int ssum[1024];
    int tid = threadIdx.x;
    int begin = tid * CH;
    int endi = begin + CH; if (endi > N_NODES) endi = N_NODES;
    int s = 0;
    for (int i = begin; i < endi; i++) s += g_zs.cnt[i];
    ssum[tid] = s;
    __syncthreads();
    for (int off = 1; off < 1024; off <<= 1) {
        int v = 0;
        if (tid >= off) v = ssum[tid - off];
        __syncthreads();
        ssum[tid] += v;
        __syncthreads();
    }
    int run = ssum[tid] - s;
    for (int i = begin; i < endi; i++) {
        g_off[i] = run;
        g_cur[i] = run;
        run += g_zs.cnt[i];
    }
    if (tid == 1023) g_off[N_NODES] = ssum[1023];
}

__global__ void fill_kernel(const int* __restrict__ ei) {
    int e = blockIdx.x * 256 + threadIdx.x;
    if (e < N_EDGES) {
        int s = ei[e], d = ei[N_EDGES + e];
        int p = atomicAdd(&g_cur[s], 1);
        g_incid[p] = make_int2(e << 1, d);
        int p2 = atomicAdd(&g_cur[d], 1);
        g_incid[p2] = make_int2((e << 1) | 1, s);
    }
}

// ---------------- combined weights: Wc = Wab @ Win2, bc = Wab @ bin2 -----
__global__ __launch_bounds__(256)
void wc_kernel(const float* __restrict__ Wm1,
               const float* __restrict__ Win2,
               const float* __restrict__ bin2)
{
    __shared__ float part[256];
    __shared__ float bpart[64];
    int i = blockIdx.x;
    const float* wrow = (i < 64) ? &Wm1[i * 512] : &Wm1[(i - 64) * 512 + 256];
    int t = threadIdx.x;
    int mh = t & 63, kq = t >> 6;
    float s = 0.f;
    #pragma unroll 16
    for (int k = kq * 64; k < kq * 64 + 64; k++)
        s += wrow[k] * Win2[k * 64 + mh];
    part[t] = s;
    if (kq == 0) {
        float b = 0.f;
        #pragma unroll
        for (int k = mh * 4; k < mh * 4 + 4; k++) b += wrow[k] * bin2[k];
        bpart[mh] = b;
    }
    __syncthreads();
    if (kq == 0)
        g_Wc[i * 64 + mh] = part[mh] + part[64 + mh] + part[128 + mh] + part[192 + mh];
    if (t == 0) {
        float bb = 0.f;
        #pragma unroll
        for (int k = 0; k < 64; k++) bb += bpart[k];
        g_bc[i] = bb;
    }
}

// ---------------- per-edge v4: weights-in-regs, 20 edges/warp, shfl fsft -
__global__ __launch_bounds__(256, 2)
void edge_kernel(const int* __restrict__ ei, const float* __restrict__ Wm2,
                 const float* __restrict__ bm1, const float* __restrict__ bm2)
{
    __shared__ float W4s[1024];
    __shared__ float sbuf[8 * 128];
    int tid = threadIdx.x;
    for (int idx = tid; idx < 1024; idx += 256) {
        int o = idx >> 6, k = idx & 63;
        W4s[((k >> 2) << 6) + (o << 2) + (k & 3)] = Wm2[idx];
    }
    __syncthreads();

    int warp = tid >> 5, lane = tid & 31;
    int o = lane & 15;
    float* sw = &sbuf[warp * 128];
    int k0 = lane * 2;

    float4 wreg[16];
    #pragma unroll
    for (int kc = 0; kc < 16; kc++)
        wreg[kc] = *(const float4*)&W4s[kc * 64 + o * 4];
    float2 b1 = *(const float2*)&bm1[k0];
    float bm2o = __ldg(&bm2[o]);
    int i = o >> 2, j = o & 3;

    const int EPW = 20;
    int e0 = (blockIdx.x * 8 + warp) * EPW;  // grid 1250, exact

    int sA = ei[e0], dA = ei[N_EDGES + e0];
    float2 AsA = *(const float2*)&g_AB[sA * 128 + k0];
    float2 BdA = *(const float2*)&g_AB[dA * 128 + 64 + k0];
    float2 AdA = *(const float2*)&g_AB[dA * 128 + k0];
    float2 BsA = *(const float2*)&g_AB[sA * 128 + 64 + k0];

    #pragma unroll 4
    for (int t = 0; t < EPW; t++) {
        int e = e0 + t;
        int sB = 0, dB = 0;
        float2 AsB, BdB, AdB, BsB;
        if (t < EPW - 1) {
            sB = ei[e + 1]; dB = ei[N_EDGES + e + 1];
            AsB = *(const float2*)&g_AB[sB * 128 + k0];
            BdB = *(const float2*)&g_AB[dB * 128 + 64 + k0];
            AdB = *(const float2*)&g_AB[dB * 128 + k0];
            BsB = *(const float2*)&g_AB[sB * 128 + 64 + k0];
        }

        float2 t1v = make_float2(fmaxf(AsA.x + BdA.x + b1.x, 0.f),
                                 fmaxf(AsA.y + BdA.y + b1.y, 0.f));
        float2 t2v = make_float2(fmaxf(AdA.x + BsA.x + b1.x, 0.f),
                                 fmaxf(AdA.y + BsA.y + b1.y, 0.f));
        __syncwarp();
        *(float2*)&sw[k0]      = t1v;
        *(float2*)&sw[64 + k0] = t2v;
        __syncwarp();

        const float* tv = sw + ((lane >> 4) << 6);
        float accf = 0.f;
        #pragma unroll
        for (int kc = 0; kc < 16; kc++) {
            float4 tval = *(const float4*)&tv[kc * 4];
            float4 w = wreg[kc];
            accf += tval.x * w.x + tval.y * w.y + tval.z * w.z + tval.w * w.w;
        }
        accf += bm2o;

        float p = 0.f, q = 0.f, ss = 0.f;
        #pragma unroll
        for (int m = 0; m < 4; m++) {
            float fsi = __shfl_sync(0xffffffffu, accf, m * 4 + i);
            float fsj = __shfl_sync(0xffffffffu, accf, m * 4 + j);
            float fti = __shfl_sync(0xffffffffu, accf, 16 + m * 4 + i);
            float ftj = __shfl_sync(0xffffffffu, accf, 16 + m * 4 + j);
            p  += fsi * fsj;
            q  += fsi * ftj;
            ss += fti * ftj;
        }
        if (lane < 16) {
            float* qb = &g_Q[(size_t)e * 32];
            qb[lane] = q;
            qb[16 + j * 4 + i] = q;
            atomicAdd(&g_zs.D[sA * 16 + lane], p);
            atomicAdd(&g_zs.D[dA * 16 + lane], ss);
        }

        sA = sB; dA = dB;
        AsA = AsB; BdA = BdB; AdA = AdB; BsA = BsB;
    }
}

// ---------------- per-node H = (Wd1^T @ xb) @ Wd2^T ----------------------
__global__ __launch_bounds__(256)
void hcomp_kernel(const float* __restrict__ Wd1, const float* __restrict__ Wd2,
                  int layer, int nbase)
{
    __shared__ float w2s[64 * 65];
    __shared__ float h1s[8][4][64];
    int tid = threadIdx.x;
    for (int idx = tid; idx < 4096; idx += 256) {
        int g = idx >> 6, f = idx & 63;
        w2s[g * 65 + f] = Wd2[layer * 4096 + idx];
    }
    float wd1[16];
    #pragma unroll
    for (int i = 0; i < 16; i++) wd1[i] = __ldg(&Wd1[layer * 16 + i]);

    int warp = tid >> 5, lane = tid & 31;
    int n = nbase + blockIdx.x * 8 + warp;
    int c0 = lane * 2;
    float2 xv[4];
    #pragma unroll
    for (int j = 0; j < 4; j++)
        xv[j] = *(const float2*)&g_h[n * 256 + j * 64 + c0];
    #pragma unroll
    for (int i = 0; i < 4; i++) {
        h1s[warp][i][c0]     = wd1[i] * xv[0].x + wd1[4 + i] * xv[1].x +
                               wd1[8 + i] * xv[2].x + wd1[12 + i] * xv[3].x;
        h1s[warp][i][c0 + 1] = wd1[i] * xv[0].y + wd1[4 + i] * xv[1].y +
                               wd1[8 + i] * xv[2].y + wd1[12 + i] * xv[3].y;
    }
    __syncthreads();

    int ca = lane, cb = lane + 32;
    float acca[4] = {0, 0, 0, 0};
    float accb[4] = {0, 0, 0, 0};
    #pragma unroll
    for (int f0 = 0; f0 < 64; f0 += 4) {
        float4 h0 = *(const float4*)&h1s[warp][0][f0];
        float4 h1 = *(const float4*)&h1s[warp][1][f0];
        float4 h2 = *(const float4*)&h1s[warp][2][f0];
        float4 h3 = *(const float4*)&h1s[warp][3][f0];
        const float* wa = &w2s[ca * 65 + f0];
        const float* wb = &w2s[cb * 65 + f0];
        float wa0 = wa[0], wa1 = wa[1], wa2 = wa[2], wa3 = wa[3];
        float wb0 = wb[0], wb1 = wb[1], wb2 = wb[2], wb3 = wb[3];
        acca[0] += h0.x * wa0 + h0.y * wa1 + h0.z * wa2 + h0.w * wa3;
        acca[1] += h1.x * wa0 + h1.y * wa1 + h1.z * wa2 + h1.w * wa3;
        acca[2] += h2.x * wa0 + h2.y * wa1 + h2.z * wa2 + h2.w * wa3;
        acca[3] += h3.x * wa0 + h3.y * wa1 + h3.z * wa2 + h3.w * wa3;
        accb[0] += h0.x * wb0 + h0.y * wb1 + h0.z * wb2 + h0.w * wb3;
        accb[1] += h1.x * wb0 + h1.y * wb1 + h1.z * wb2 + h1.w * wb3;
        accb[2] += h2.x * wb0 + h2.y * wb1 + h2.z * wb2 + h2.w * wb3;
        accb[3] += h3.x * wb0 + h3.y * wb1 + h3.z * wb2 + h3.w * wb3;
    }
    #pragma unroll
    for (int k = 0; k < 4; k++) {
        g_H[n * 256 + k * 64 + ca] = acca[k];
        g_H[n * 256 + k * 64 + cb] = accb[k];
    }
}

// ---------------- gather: 5 LDG per incidence, deferred butterfly --------
__device__ __forceinline__ void proc_inc2(int idx, int g, int cl, float part[4][4])
{
    int2 v = __ldg(&g_incid[idx]);
    int e = v.x >> 1, role = v.x & 1;
    int other = v.y;
    const float* qb = &g_Q[(size_t)e * 32 + (role ? 0 : 16)];
    const float* hb = &g_H[(size_t)other * 256 + cl * 4];

    #pragma unroll
    for (int jj = 0; jj < 2; jj++) {
        int j = g + jj * 2;
        float4 qv = *(const float4*)&qb[j * 4];
        float4 hv = *(const float4*)&hb[j * 64];
        part[0][0] += qv.x * hv.x; part[0][1] += qv.x * hv.y;
        part[0][2] += qv.x * hv.z; part[0][3] += qv.x * hv.w;
        part[1][0] += qv.y * hv.x; part[1][1] += qv.y * hv.y;
        part[1][2] += qv.y * hv.z; part[1][3] += qv.y * hv.w;
        part[2][0] += qv.z * hv.x; part[2][1] += qv.z * hv.y;
        part[2][2] += qv.z * hv.z; part[2][3] += qv.z * hv.w;
        part[3][0] += qv.w * hv.x; part[3][1] += qv.w * hv.y;
        part[3][2] += qv.w * hv.z; part[3][3] += qv.w * hv.w;
    }
}

__global__ __launch_bounds__(256)
void gather_kernel()
{
    __shared__ float red[4][32][16];
    int warp = threadIdx.x >> 5, lane = threadIdx.x & 31;
    int slot = warp >> 1, w2 = warp & 1;
    int n = blockIdx.x * 4 + slot;     // grid 5000, exact
    int beg = g_off[n], endi = g_off[n + 1];
    int cnt = endi - beg;
    int mid = beg + ((cnt + 1) >> 1);
    int lo = w2 ? mid : beg;
    int hi = w2 ? endi : mid;
    int g = lane >> 4, cl = lane & 15;

    float part[4][4] = {};

    int idx = lo;
    for (; idx + 1 < hi; idx += 2) {
        proc_inc2(idx,     g, cl, part);
        proc_inc2(idx + 1, g, cl, part);
    }
    if (idx < hi) proc_inc2(idx, g, cl, part);

    if (w2) {
        #pragma unroll
        for (int i = 0; i < 4; i++)
            #pragma unroll
            for (int c = 0; c < 4; c++)
                red[slot][lane][i * 4 + c] = part[i][c];
    }
    __syncthreads();
    if (!w2) {
        #pragma unroll
        for (int i = 0; i < 4; i++)
            #pragma unroll
            for (int c = 0; c < 4; c++)
                part[i][c] += red[slot][lane][i * 4 + c];

        const float* db = &g_zs.D[n * 16];
        const float* hb = &g_H[(size_t)n * 256 + cl * 4];
        float lh[4][4];
        {
            float4 qv0 = *(const float4*)&db[g * 4];
            float4 hv0 = *(const float4*)&hb[g * 64];
            float4 qv1 = *(const float4*)&db[(g + 2) * 4];
            float4 hv1 = *(const float4*)&hb[(g + 2) * 64];
            #pragma unroll
            for (int i = 0; i < 4; i++) {
                float qi0 = (i == 0 ? qv0.x : i == 1 ? qv0.y : i == 2 ? qv0.z : qv0.w);
                float qi1 = (i == 0 ? qv1.x : i == 1 ? qv1.y : i == 2 ? qv1.z : qv1.w);
                lh[i][0] = qi0 * hv0.x + qi1 * hv1.x - part[i][0];
                lh[i][1] = qi0 * hv0.y + qi1 * hv1.y - part[i][1];
                lh[i][2] = qi0 * hv0.z + qi1 * hv1.z - part[i][2];
                lh[i][3] = qi0 * hv0.w + qi1 * hv1.w - part[i][3];
            }
        }
        #pragma unroll
        for (int i = 0; i < 4; i++)
            #pragma unroll
            for (int c = 0; c < 4; c++)
                lh[i][c] += __shfl_xor_sync(0xffffffffu, lh[i][c], 16);

        #pragma unroll
        for (int r = 0; r < 2; r++) {
            int i = g * 2 + r;
            float* xp = &g_h[(size_t)n * 256 + i * 64 + cl * 4];
            float4 xv = *(const float4*)xp;
            xv.x -= fmaxf(lh[i][0], 0.f);
            xv.y -= fmaxf(lh[i][1], 0.f);
            xv.z -= fmaxf(lh[i][2], 0.f);
            xv.w -= fmaxf(lh[i][3], 0.f);
            *(float4*)xp = xv;
        }
    }
}

// ---------------- launch (stream-forked DAG) ----------------
static cudaStream_t s_s1, s_s2;
static cudaEvent_t  s_evRoot, s_evG1b, s_evWc, s_evMs, s_evG1, s_evH,
                    s_evHc0A, s_evHc0B, s_evFill;
static bool s_init = false;

extern "C" void kernel_launch(void* const* d_in, const int* in_sizes, int n_in,
                              void* d_out, int out_size)
{
    const float* x    = (const float*)d_in[0];
    const int*   ei   = (const int*)  d_in[1];
    const float* Win1 = (const float*)d_in[2];
    const float* bin1 = (const float*)d_in[3];
    const float* Win2 = (const float*)d_in[4];
    const float* bin2 = (const float*)d_in[5];
    const float* Wm1  = (const float*)d_in[6];
    const float* bm1  = (const float*)d_in[7];
    const float* Wm2  = (const float*)d_in[8];
    const float* bm2  = (const float*)d_in[9];
    const float* Wd1  = (const float*)d_in[10];
    const float* Wd2  = (const float*)d_in[11];
    const float* Wo1  = (const float*)d_in[12];
    const float* bo1  = (const float*)d_in[13];
    const float* Wo2  = (const float*)d_in[14];
    const float* bo2  = (const float*)d_in[15];
    float* out = (float*)d_out;

    if (!s_init) {
        cudaStreamCreateWithFlags(&s_s1, cudaStreamNonBlocking);
        cudaStreamCreateWithFlags(&s_s2, cudaStreamNonBlocking);
        cudaEventCreateWithFlags(&s_evRoot, cudaEventDisableTiming);
        cudaEventCreateWithFlags(&s_evG1b,  cudaEventDisableTiming);
        cudaEventCreateWithFlags(&s_evWc,   cudaEventDisableTiming);
        cudaEventCreateWithFlags(&s_evMs,   cudaEventDisableTiming);
        cudaEventCreateWithFlags(&s_evG1,   cudaEventDisableTiming);
        cudaEventCreateWithFlags(&s_evH,    cudaEventDisableTiming);
        cudaEventCreateWithFlags(&s_evHc0A, cudaEventDisableTiming);
        cudaEventCreateWithFlags(&s_evHc0B, cudaEventDisableTiming);
        cudaEventCreateWithFlags(&s_evFill, cudaEventDisableTiming);
        s_init = true;
    }

    void *p_zs, *p_h, *p_h1, *p_p0, *p_p1, *p_AB, *p_Wc, *p_bc;
    cudaGetSymbolAddress(&p_zs, g_zs);
    cudaGetSymbolAddress(&p_h,  g_h);
    cudaGetSymbolAddress(&p_h1, g_h1);
    cudaGetSymbolAddress(&p_p0, g_p0);
    cudaGetSymbolAddress(&p_p1, g_p1);
    cudaGetSymbolAddress(&p_AB, g_AB);
    cudaGetSymbolAddress(&p_Wc, g_Wc);
    cudaGetSymbolAddress(&p_bc, g_bc);
    float* h   = (float*)p_h;
    float* h1  = (float*)p_h1;
    float* P0  = (float*)p_p0;
    float* P1  = (float*)p_p1;
    float* AB  = (float*)p_AB;
    float* Wc  = (float*)p_Wc;
    float* bc  = (float*)p_bc;

    const int MB = (N_NODES + 127) / 128;  // 157

    // ---- fork side streams off the capture-origin stream (0) ----
    cudaEventRecord(s_evRoot, 0);
    cudaStreamWaitEvent(s_s1, s_evRoot, 0);
    cudaStreamWaitEvent(s_s2, s_evRoot, 0);

    // ---- s2: weights-combine + CSR chain ----
    wc_kernel<<<128, 256, 0, s_s2>>>(Wm1, Win2, bin2);
    cudaEventRecord(s_evWc, s_s2);
    cudaMemsetAsync(p_zs, 0, sizeof(ZS), s_s2);
    cudaEventRecord(s_evMs, s_s2);
    count_kernel<<<(N_EDGES + 255) / 256, 256, 0, s_s2>>>(ei);
    scan_kernel<<<1, 1024, 0, s_s2>>>();
    fill_kernel<<<(N_EDGES + 255) / 256, 256, 0, s_s2>>>(ei);
    cudaEventRecord(s_evFill, s_s2);

    // ---- s1: second split-K half of input MLP ----
    sgemm128<false, false><<<dim3(1, MB), 256, 0, s_s1>>>(
        x + 256, nullptr, nullptr, Win1 + 256, nullptr, P1,
        N_NODES, 64, 244, IN_DIM, IN_DIM);
    cudaEventRecord(s_evG1b, s_s1);

    // ---- stream 0: critical path to edge (AB reads P0/P1 directly) ----
    sgemm128<false, false><<<dim3(1, MB), 256>>>(
        x, nullptr, nullptr, Win1, nullptr, P0,
        N_NODES, 64, 256, IN_DIM, IN_DIM);
    cudaStreamWaitEvent(0, s_evG1b, 0);
    cudaEventRecord(s_evG1, 0);            // P0 & P1 ready
    cudaStreamWaitEvent(0, s_evWc, 0);
    sgemm128<false, true><<<dim3(2, MB), 256>>>(
        P0, P1, bin1, Wc, bc, AB, N_NODES, 128, 64, 64, 64);
    cudaStreamWaitEvent(0, s_evMs, 0);
    edge_kernel<<<N_EDGES / 160, 256>>>(ei, Wm2, bm1, bm2);

    // ---- s1: combine -> h = h1@Win2^T + bin2; hcomp0 split A(s1)/B(s2) ----
    cudaStreamWaitEvent(s_s1, s_evG1, 0);
    combine_kernel<<<(N_NODES * 64 / 4 + 255) / 256, 256, 0, s_s1>>>(bin1);
    sgemm128<false, false><<<dim3(4, MB), 256, 0, s_s1>>>(
        h1, nullptr, nullptr, Win2, bin2, h, N_NODES, 256, 64, 64, 64);
    cudaEventRecord(s_evH, s_s1);
    hcomp_kernel<<<1250, 256, 0, s_s1>>>(Wd1, Wd2, 0, 0);       // nodes 0..9999
    cudaEventRecord(s_evHc0A, s_s1);
    cudaStreamWaitEvent(s_s2, s_evH, 0);
    hcomp_kernel<<<1250, 256, 0, s_s2>>>(Wd1, Wd2, 0, 10000);   // nodes 10000..19999
    cudaEventRecord(s_evHc0B, s_s2);

    // ---- join: gather layer 0 needs edge(0) + fill(s2) + hcomp0 A&B ----
    cudaStreamWaitEvent(0, s_evFill, 0);
    cudaStreamWaitEvent(0, s_evHc0A, 0);
    cudaStreamWaitEvent(0, s_evHc0B, 0);
    gather_kernel<<<N_NODES / 4, 256>>>();
    hcomp_kernel<<<N_NODES / 8, 256>>>(Wd1, Wd2, 1, 0);
    gather_kernel<<<N_NODES / 4, 256>>>();

    // ---- fused output MLP ----
    outmlp_kernel<<<MB, 256>>>(h, Wo1, bo1, Wo2, bo2, out);
}